// round 12
// baseline (speedup 1.0000x reference)
#include <cuda_runtime.h>
#include <cstdint>

// WeightedRuleLayer: out[r,:] = tanh( sum_p layer_values[idx[r,p],:] * weights[r,p,:] )
// D=128, P=8.
//
// Bottleneck analysis (R7): LSU issue floor (~1.82 cyc/LDG/SM) is co-binding with
// DRAM. Fix: weights+indices for a CTA's 8 rules are contiguous -> one
// cp.async.bulk (UBLKCP) into smem instead of 17 per-warp LDGs per rule.
// Only the random gather (8 LDG.128) + store stay on the LSU.

#define D_DIM 128
#define PERIOD 8
#define RULES_PER_CTA 8
#define THREADS 256

__device__ int g_idx_is64;

// Detect int64 vs int32 indices: values < 2e5, so for int64 every odd 32-bit
// word is 0; for int32 odd words are random (P all-zero ~ (5e-6)^512 ~ 0).
__global__ void detect_idx_dtype(const unsigned int* __restrict__ ind_words) {
    const int lane = threadIdx.x & 31;
    unsigned int acc = 0;
    #pragma unroll
    for (int i = 0; i < 16; ++i)
        acc |= ind_words[2 * (lane * 16 + i) + 1];
    #pragma unroll
    for (int off = 16; off > 0; off >>= 1)
        acc |= __shfl_xor_sync(0xFFFFFFFFu, acc, off);
    if (lane == 0) g_idx_is64 = (acc == 0u) ? 1 : 0;
}

__global__ __launch_bounds__(THREADS) void weighted_rule_kernel(
    const float* __restrict__ lv,      // [N_SRC, 128]  random gather (LDG)
    const float* __restrict__ w,       // [R, 8, 128]   contiguous -> bulk copy
    const char*  __restrict__ ind,     // [R, 8] int32 or int64 -> bulk copy
    float* __restrict__ out,           // [R, 128]
    int nrules)
{
    __shared__ alignas(128) float s_w[RULES_PER_CTA * PERIOD * D_DIM]; // 32 KB
    __shared__ alignas(16) unsigned char s_idx[RULES_PER_CTA * PERIOD * 8]; // 512 B
    __shared__ alignas(8) unsigned long long s_mbar;

    const int tid  = threadIdx.x;
    const int warp = tid >> 5;
    const int lane = tid & 31;
    const long long r0 = (long long)blockIdx.x * RULES_PER_CTA;
    const int rules_here = (nrules - (int)r0 < RULES_PER_CTA)
                               ? (nrules - (int)r0) : RULES_PER_CTA;
    const int is64 = g_idx_is64;

    const unsigned int mbar_a  = (unsigned int)__cvta_generic_to_shared(&s_mbar);
    const unsigned int s_w_a   = (unsigned int)__cvta_generic_to_shared(s_w);
    const unsigned int s_idx_a = (unsigned int)__cvta_generic_to_shared(s_idx);

    if (tid == 0) {
        asm volatile("mbarrier.init.shared.b64 [%0], 1;" :: "r"(mbar_a) : "memory");
    }
    __syncthreads();

    if (tid == 0) {
        const unsigned int w_bytes   = (unsigned int)rules_here * PERIOD * D_DIM * 4;
        const unsigned int idx_bytes = (unsigned int)rules_here * PERIOD * (is64 ? 8 : 4);
        asm volatile("mbarrier.arrive.expect_tx.shared.b64 _, [%0], %1;"
                     :: "r"(mbar_a), "r"(w_bytes + idx_bytes) : "memory");
        const float* wsrc = w + r0 * PERIOD * D_DIM;
        asm volatile(
            "cp.async.bulk.shared::cta.global.mbarrier::complete_tx::bytes "
            "[%0], [%1], %2, [%3];"
            :: "r"(s_w_a), "l"(wsrc), "r"(w_bytes), "r"(mbar_a) : "memory");
        const char* isrc = ind + r0 * PERIOD * (is64 ? 8 : 4);
        asm volatile(
            "cp.async.bulk.shared::cta.global.mbarrier::complete_tx::bytes "
            "[%0], [%1], %2, [%3];"
            :: "r"(s_idx_a), "l"(isrc), "r"(idx_bytes), "r"(mbar_a) : "memory");
    }

    // Wait (phase 0), acquire so the LDS reads below see the bulk-copied data.
    {
        unsigned int done;
        asm volatile(
            "{\n\t"
            ".reg .pred p;\n\t"
            "mbarrier.try_wait.parity.acquire.cta.shared::cta.b64 p, [%1], %2;\n\t"
            "selp.b32 %0, 1, 0, p;\n\t"
            "}"
            : "=r"(done) : "r"(mbar_a), "r"(0) : "memory");
        if (!done) {
            asm volatile(
                "{\n\t"
                ".reg .pred P1;\n\t"
                "WAIT_LOOP:\n\t"
                "mbarrier.try_wait.parity.acquire.cta.shared::cta.b64 P1, [%0], %1, 0x989680;\n\t"
                "@P1 bra.uni WAIT_DONE;\n\t"
                "bra.uni WAIT_LOOP;\n\t"
                "WAIT_DONE:\n\t"
                "}"
                :: "r"(mbar_a), "r"(0) : "memory");
        }
    }

    if (warp >= rules_here) return;

    // Indices for this warp's rule (uniform across warp -> LDS broadcast).
    int idx[PERIOD];
    if (is64) {
        const long long* ip = (const long long*)s_idx + warp * PERIOD;
        #pragma unroll
        for (int p = 0; p < PERIOD; ++p) idx[p] = (int)ip[p];
    } else {
        const int* ip = (const int*)s_idx + warp * PERIOD;
        #pragma unroll
        for (int p = 0; p < PERIOD; ++p) idx[p] = ip[p];
    }

    const float4* swp = (const float4*)(s_w + warp * PERIOD * D_DIM) + lane;

    float4 acc = make_float4(0.f, 0.f, 0.f, 0.f);
    #pragma unroll
    for (int p = 0; p < PERIOD; ++p) {
        float4 wv = swp[p * 32];                             // LDS.128, conflict-free
        const float4* xp = (const float4*)(lv + (size_t)idx[p] * D_DIM) + lane;
        float4 xv = __ldg(xp);                               // random gather
        acc.x = fmaf(wv.x, xv.x, acc.x);
        acc.y = fmaf(wv.y, xv.y, acc.y);
        acc.z = fmaf(wv.z, xv.z, acc.z);
        acc.w = fmaf(wv.w, xv.w, acc.w);
    }

    float4 res;
    res.x = tanhf(acc.x);
    res.y = tanhf(acc.y);
    res.z = tanhf(acc.z);
    res.w = tanhf(acc.w);

    float4* op = (float4*)(out + (r0 + warp) * D_DIM) + lane;
    __stcs(op, res);                                         // write-once stream
}

extern "C" void kernel_launch(void* const* d_in, const int* in_sizes, int n_in,
                              void* d_out, int out_size) {
    const float* lv  = (const float*)d_in[0];   // layer_values [200000,128]
    const float* w   = (const float*)d_in[1];   // weights [R,8,128]
    const char*  ind = (const char*)d_in[2];    // indices [R,8]

    const int nrules = in_sizes[2] / PERIOD;

    detect_idx_dtype<<<1, 32>>>((const unsigned int*)ind);

    const int blocks = (nrules + RULES_PER_CTA - 1) / RULES_PER_CTA;
    weighted_rule_kernel<<<blocks, THREADS>>>(lv, w, ind, (float*)d_out, nrules);
}

// round 13
// speedup vs baseline: 1.0718x; 1.0718x over previous
#include <cuda_runtime.h>
#include <cstdint>

// WeightedRuleLayer: out[r,:] = tanh( sum_p layer_values[idx[r,p],:] * weights[r,p,:] )
// D=128, P=8.
//
// R12 lesson: cp.async.bulk without a cache hint lets the 1.02GB weights
// stream churn layer_values (102MB, ~10x reuse) out of L2 -> +0.28GB DRAM.
// Fix: evict_first policy on the bulk copies (same semantics __ldcs gave the
// old LDG path) while keeping the LSU-offloaded UBLKCP+LDS structure that
// raised sustained DRAM to ~89% of peak.

#define D_DIM 128
#define PERIOD 8
#define RULES_PER_CTA 8
#define THREADS 256

__device__ int g_idx_is64;

// Detect int64 vs int32 indices: values < 2e5, so for int64 every odd 32-bit
// word is 0; for int32 odd words are random (P all-zero ~ (5e-6)^512 ~ 0).
__global__ void detect_idx_dtype(const unsigned int* __restrict__ ind_words) {
    const int lane = threadIdx.x & 31;
    unsigned int acc = 0;
    #pragma unroll
    for (int i = 0; i < 16; ++i)
        acc |= ind_words[2 * (lane * 16 + i) + 1];
    #pragma unroll
    for (int off = 16; off > 0; off >>= 1)
        acc |= __shfl_xor_sync(0xFFFFFFFFu, acc, off);
    if (lane == 0) g_idx_is64 = (acc == 0u) ? 1 : 0;
}

__global__ __launch_bounds__(THREADS) void weighted_rule_kernel(
    const float* __restrict__ lv,      // [N_SRC, 128]  random gather (LDG, L2-resident)
    const float* __restrict__ w,       // [R, 8, 128]   contiguous -> bulk copy, evict_first
    const char*  __restrict__ ind,     // [R, 8] int32 or int64 -> bulk copy
    float* __restrict__ out,           // [R, 128]
    int nrules)
{
    __shared__ alignas(128) float s_w[RULES_PER_CTA * PERIOD * D_DIM]; // 32 KB
    __shared__ alignas(16) unsigned char s_idx[RULES_PER_CTA * PERIOD * 8]; // 512 B
    __shared__ alignas(8) unsigned long long s_mbar;

    const int tid  = threadIdx.x;
    const int warp = tid >> 5;
    const int lane = tid & 31;
    const long long r0 = (long long)blockIdx.x * RULES_PER_CTA;
    const int rules_here = (nrules - (int)r0 < RULES_PER_CTA)
                               ? (nrules - (int)r0) : RULES_PER_CTA;
    const int is64 = g_idx_is64;

    const unsigned int mbar_a  = (unsigned int)__cvta_generic_to_shared(&s_mbar);
    const unsigned int s_w_a   = (unsigned int)__cvta_generic_to_shared(s_w);
    const unsigned int s_idx_a = (unsigned int)__cvta_generic_to_shared(s_idx);

    if (tid == 0) {
        asm volatile("mbarrier.init.shared.b64 [%0], 1;" :: "r"(mbar_a) : "memory");
    }
    __syncthreads();

    if (tid == 0) {
        const unsigned int w_bytes   = (unsigned int)rules_here * PERIOD * D_DIM * 4;
        const unsigned int idx_bytes = (unsigned int)rules_here * PERIOD * (is64 ? 8 : 4);
        asm volatile("mbarrier.arrive.expect_tx.shared.b64 _, [%0], %1;"
                     :: "r"(mbar_a), "r"(w_bytes + idx_bytes) : "memory");

        // Streamed-once data: evict_first so it can't churn lv out of L2.
        unsigned long long pol;
        asm("createpolicy.fractional.L2::evict_first.b64 %0, 1.0;" : "=l"(pol));

        const float* wsrc = w + r0 * PERIOD * D_DIM;
        asm volatile(
            "cp.async.bulk.shared::cta.global.mbarrier::complete_tx::bytes.L2::cache_hint "
            "[%0], [%1], %2, [%3], %4;"
            :: "r"(s_w_a), "l"(wsrc), "r"(w_bytes), "r"(mbar_a), "l"(pol) : "memory");
        const char* isrc = ind + r0 * PERIOD * (is64 ? 8 : 4);
        asm volatile(
            "cp.async.bulk.shared::cta.global.mbarrier::complete_tx::bytes.L2::cache_hint "
            "[%0], [%1], %2, [%3], %4;"
            :: "r"(s_idx_a), "l"(isrc), "r"(idx_bytes), "r"(mbar_a), "l"(pol) : "memory");
    }

    // Wait (phase 0), acquire so the LDS reads below see the bulk-copied data.
    {
        unsigned int done;
        asm volatile(
            "{\n\t"
            ".reg .pred p;\n\t"
            "mbarrier.try_wait.parity.acquire.cta.shared::cta.b64 p, [%1], %2;\n\t"
            "selp.b32 %0, 1, 0, p;\n\t"
            "}"
            : "=r"(done) : "r"(mbar_a), "r"(0) : "memory");
        if (!done) {
            asm volatile(
                "{\n\t"
                ".reg .pred P1;\n\t"
                "WAIT_LOOP:\n\t"
                "mbarrier.try_wait.parity.acquire.cta.shared::cta.b64 P1, [%0], %1, 0x989680;\n\t"
                "@P1 bra.uni WAIT_DONE;\n\t"
                "bra.uni WAIT_LOOP;\n\t"
                "WAIT_DONE:\n\t"
                "}"
                :: "r"(mbar_a), "r"(0) : "memory");
        }
    }

    if (warp >= rules_here) return;

    // Indices for this warp's rule (uniform across warp -> LDS broadcast).
    int idx[PERIOD];
    if (is64) {
        const long long* ip = (const long long*)s_idx + warp * PERIOD;
        #pragma unroll
        for (int p = 0; p < PERIOD; ++p) idx[p] = (int)ip[p];
    } else {
        const int* ip = (const int*)s_idx + warp * PERIOD;
        #pragma unroll
        for (int p = 0; p < PERIOD; ++p) idx[p] = ip[p];
    }

    const float4* swp = (const float4*)(s_w + warp * PERIOD * D_DIM) + lane;

    float4 acc = make_float4(0.f, 0.f, 0.f, 0.f);
    #pragma unroll
    for (int p = 0; p < PERIOD; ++p) {
        float4 wv = swp[p * 32];                             // LDS.128, conflict-free
        const float4* xp = (const float4*)(lv + (size_t)idx[p] * D_DIM) + lane;
        float4 xv = __ldg(xp);                               // random gather, L2-resident
        acc.x = fmaf(wv.x, xv.x, acc.x);
        acc.y = fmaf(wv.y, xv.y, acc.y);
        acc.z = fmaf(wv.z, xv.z, acc.z);
        acc.w = fmaf(wv.w, xv.w, acc.w);
    }

    float4 res;
    res.x = tanhf(acc.x);
    res.y = tanhf(acc.y);
    res.z = tanhf(acc.z);
    res.w = tanhf(acc.w);

    float4* op = (float4*)(out + (r0 + warp) * D_DIM) + lane;
    __stcs(op, res);                                         // write-once stream
}

extern "C" void kernel_launch(void* const* d_in, const int* in_sizes, int n_in,
                              void* d_out, int out_size) {
    const float* lv  = (const float*)d_in[0];   // layer_values [200000,128]
    const float* w   = (const float*)d_in[1];   // weights [R,8,128]
    const char*  ind = (const char*)d_in[2];    // indices [R,8]

    const int nrules = in_sizes[2] / PERIOD;

    detect_idx_dtype<<<1, 32>>>((const unsigned int*)ind);

    const int blocks = (nrules + RULES_PER_CTA - 1) / RULES_PER_CTA;
    weighted_rule_kernel<<<blocks, THREADS>>>(lv, w, ind, (float*)d_out, nrules);
}

// round 14
// speedup vs baseline: 1.1230x; 1.0478x over previous
#include <cuda_runtime.h>
#include <cstdint>

// WeightedRuleLayer: out[r,:] = tanh( sum_p layer_values[idx[r,p],:] * weights[r,p,:] )
// D=128, P=8.
//
// R13 finding: reads marked streaming/evict-first (either .cs LDG or bulk
// .L2::cache_hint evict_first) cap the 1.15GB weights/out stream at ~5.1TB/s;
// evict-normal bulk (R12) streamed at ~7.1TB/s but churned layer_values out
// of L2 (+0.27GB misses). Resolution: evict-normal bulk copy for speed, then
// discard.global.L2 the consumed weight lines immediately (weights are
// single-use, single-CTA, read-only -> clean lines; DRAM copy stays intact
// for the next graph replay). L2 keeps ~100MB free for layer_values.

#define D_DIM 128
#define PERIOD 8
#define RULES_PER_CTA 8
#define THREADS 256

__device__ int g_idx_is64;

// Detect int64 vs int32 indices: values < 2e5, so for int64 every odd 32-bit
// word is 0; for int32 odd words are random (P all-zero ~ (5e-6)^512 ~ 0).
__global__ void detect_idx_dtype(const unsigned int* __restrict__ ind_words) {
    const int lane = threadIdx.x & 31;
    unsigned int acc = 0;
    #pragma unroll
    for (int i = 0; i < 16; ++i)
        acc |= ind_words[2 * (lane * 16 + i) + 1];
    #pragma unroll
    for (int off = 16; off > 0; off >>= 1)
        acc |= __shfl_xor_sync(0xFFFFFFFFu, acc, off);
    if (lane == 0) g_idx_is64 = (acc == 0u) ? 1 : 0;
}

__global__ __launch_bounds__(THREADS) void weighted_rule_kernel(
    const float* __restrict__ lv,      // [N_SRC, 128]  random gather, wants L2 residency
    const float* __restrict__ w,       // [R, 8, 128]   bulk copy (evict-normal) + discard
    const char*  __restrict__ ind,     // [R, 8] int32 or int64 -> bulk copy
    float* __restrict__ out,           // [R, 128]
    int nrules)
{
    __shared__ alignas(128) float s_w[RULES_PER_CTA * PERIOD * D_DIM]; // 32 KB
    __shared__ alignas(16) unsigned char s_idx[RULES_PER_CTA * PERIOD * 8]; // 512 B
    __shared__ alignas(8) unsigned long long s_mbar;

    const int tid  = threadIdx.x;
    const int warp = tid >> 5;
    const int lane = tid & 31;
    const long long r0 = (long long)blockIdx.x * RULES_PER_CTA;
    const int rules_here = (nrules - (int)r0 < RULES_PER_CTA)
                               ? (nrules - (int)r0) : RULES_PER_CTA;
    const int is64 = g_idx_is64;

    const unsigned int mbar_a  = (unsigned int)__cvta_generic_to_shared(&s_mbar);
    const unsigned int s_w_a   = (unsigned int)__cvta_generic_to_shared(s_w);
    const unsigned int s_idx_a = (unsigned int)__cvta_generic_to_shared(s_idx);

    if (tid == 0) {
        asm volatile("mbarrier.init.shared.b64 [%0], 1;" :: "r"(mbar_a) : "memory");
    }
    __syncthreads();

    const unsigned int w_bytes = (unsigned int)rules_here * PERIOD * D_DIM * 4;
    const float* wsrc = w + r0 * PERIOD * D_DIM;

    if (tid == 0) {
        const unsigned int idx_bytes = (unsigned int)rules_here * PERIOD * (is64 ? 8 : 4);
        asm volatile("mbarrier.arrive.expect_tx.shared.b64 _, [%0], %1;"
                     :: "r"(mbar_a), "r"(w_bytes + idx_bytes) : "memory");
        // Evict-normal (default) bulk copies: the fast stream path (R12: 7.1TB/s).
        asm volatile(
            "cp.async.bulk.shared::cta.global.mbarrier::complete_tx::bytes "
            "[%0], [%1], %2, [%3];"
            :: "r"(s_w_a), "l"(wsrc), "r"(w_bytes), "r"(mbar_a) : "memory");
        const char* isrc = ind + r0 * PERIOD * (is64 ? 8 : 4);
        asm volatile(
            "cp.async.bulk.shared::cta.global.mbarrier::complete_tx::bytes "
            "[%0], [%1], %2, [%3];"
            :: "r"(s_idx_a), "l"(isrc), "r"(idx_bytes), "r"(mbar_a) : "memory");
    }

    // Wait (phase 0), acquire so the LDS reads below see the bulk-copied data.
    {
        unsigned int done;
        asm volatile(
            "{\n\t"
            ".reg .pred p;\n\t"
            "mbarrier.try_wait.parity.acquire.cta.shared::cta.b64 p, [%1], %2;\n\t"
            "selp.b32 %0, 1, 0, p;\n\t"
            "}"
            : "=r"(done) : "r"(mbar_a), "r"(0) : "memory");
        if (!done) {
            asm volatile(
                "{\n\t"
                ".reg .pred P1;\n\t"
                "WAIT_LOOP:\n\t"
                "mbarrier.try_wait.parity.acquire.cta.shared::cta.b64 P1, [%0], %1, 0x989680;\n\t"
                "@P1 bra.uni WAIT_DONE;\n\t"
                "bra.uni WAIT_LOOP;\n\t"
                "WAIT_DONE:\n\t"
                "}"
                :: "r"(mbar_a), "r"(0) : "memory");
        }
    }

    // Weights consumed into smem: invalidate this CTA's weight lines in L2 so
    // they stop displacing layer_values. One 128B discard per thread covers
    // 32KB; region is 4KB-per-rule so always 128B-aligned and exclusive to
    // this CTA. Lines are clean (read-only) so DRAM keeps the data.
    {
        const unsigned int nlines = w_bytes >> 7;      // 128B lines
        if ((unsigned int)tid < nlines) {
            const char* p = (const char*)wsrc + (unsigned int)tid * 128;
            asm volatile("discard.global.L2 [%0], 128;" :: "l"(p) : "memory");
        }
    }

    if (warp >= rules_here) return;

    // Indices for this warp's rule (uniform across warp -> LDS broadcast).
    int idx[PERIOD];
    if (is64) {
        const long long* ip = (const long long*)s_idx + warp * PERIOD;
        #pragma unroll
        for (int p = 0; p < PERIOD; ++p) idx[p] = (int)ip[p];
    } else {
        const int* ip = (const int*)s_idx + warp * PERIOD;
        #pragma unroll
        for (int p = 0; p < PERIOD; ++p) idx[p] = ip[p];
    }

    const float4* swp = (const float4*)(s_w + warp * PERIOD * D_DIM) + lane;

    float4 acc = make_float4(0.f, 0.f, 0.f, 0.f);
    #pragma unroll
    for (int p = 0; p < PERIOD; ++p) {
        float4 wv = swp[p * 32];                             // LDS.128, conflict-free
        const float4* xp = (const float4*)(lv + (size_t)idx[p] * D_DIM) + lane;
        float4 xv = __ldg(xp);                               // random gather, evict-normal
        acc.x = fmaf(wv.x, xv.x, acc.x);
        acc.y = fmaf(wv.y, xv.y, acc.y);
        acc.z = fmaf(wv.z, xv.z, acc.z);
        acc.w = fmaf(wv.w, xv.w, acc.w);
    }

    float4 res;
    res.x = tanhf(acc.x);
    res.y = tanhf(acc.y);
    res.z = tanhf(acc.z);
    res.w = tanhf(acc.w);

    float4* op = (float4*)(out + (r0 + warp) * D_DIM) + lane;
    __stcs(op, res);                                         // write-once stream
}

extern "C" void kernel_launch(void* const* d_in, const int* in_sizes, int n_in,
                              void* d_out, int out_size) {
    const float* lv  = (const float*)d_in[0];   // layer_values [200000,128]
    const float* w   = (const float*)d_in[1];   // weights [R,8,128]
    const char*  ind = (const char*)d_in[2];    // indices [R,8]

    const int nrules = in_sizes[2] / PERIOD;

    detect_idx_dtype<<<1, 32>>>((const unsigned int*)ind);

    const int blocks = (nrules + RULES_PER_CTA - 1) / RULES_PER_CTA;
    weighted_rule_kernel<<<blocks, THREADS>>>(lv, w, ind, (float*)d_out, nrules);
}